// round 17
// baseline (speedup 1.0000x reference)
#include <cuda_runtime.h>
#include <cuda_fp16.h>
#include <math.h>
#include <float.h>

#define NOFF 20
#define HDIM 128
#define SEQN 8192
#define NH   16
#define NB   2
#define NQ   (NB * NH * SEQN)          // 262144 queries
#define TOTE (NQ * HDIM)
#define CVT_BLOCKS 1536
#define QSE_BLOCKS 512                  // 512*8 warps * 64 q = 262144
#define WQ 64
#define MAIN_QPW 32                     // queries per warp (consecutive)

__constant__ int c_offs[NOFF] = {1,2,3,4,5,6,7,8,9,11,13,15,16,23,32,64,128,256,512,1024};

__device__ __half g_kh[TOTE];           // fp16 mirrors
__device__ __half g_vh[TOTE];
__device__ float  g_qse[NQ * NOFF];     // (q . se_j) * sc

__device__ __forceinline__ unsigned int h2u(__half2 h) {
    union { __half2 h; unsigned int u; } c; c.h = h; return c.u;
}
__device__ __forceinline__ unsigned long long f2add(unsigned long long a, unsigned long long b) {
    unsigned long long d;
    asm("add.rn.f32x2 %0, %1, %2;" : "=l"(d) : "l"(a), "l"(b));
    return d;
}
__device__ __forceinline__ unsigned long long f2pack(float lo, float hi) {
    unsigned long long d;
    asm("mov.b64 %0, {%1, %2};" : "=l"(d) : "f"(lo), "f"(hi));
    return d;
}
__device__ __forceinline__ float2 f2unpack(unsigned long long a) {
    float lo, hi;
    asm("mov.b64 {%0, %1}, %2;" : "=f"(lo), "=f"(hi) : "l"(a));
    return make_float2(lo, hi);
}

// ==== prep: blocks [0,CVT) convert k/v to fp16 mirrors; rest compute qse ====
__global__ void __launch_bounds__(256) prep(
    const float* __restrict__ q, const float* __restrict__ k,
    const float* __restrict__ v, const float* __restrict__ se)
{
    __shared__ unsigned long long redq[8][8][10];

    if (blockIdx.x < CVT_BLOCKS) {
        const int total4 = TOTE / 4;
        for (int i = blockIdx.x * 256 + threadIdx.x; i < total4; i += CVT_BLOCKS * 256) {
            float4 a = __ldcs(((const float4*)k) + i);
            uint2 ka;
            ka.x = h2u(__floats2half2_rn(a.x, a.y));
            ka.y = h2u(__floats2half2_rn(a.z, a.w));
            ((uint2*)g_kh)[i] = ka;
            float4 b = __ldcs(((const float4*)v) + i);
            uint2 vb;
            vb.x = h2u(__floats2half2_rn(b.x, b.y));
            vb.y = h2u(__floats2half2_rn(b.z, b.w));
            ((uint2*)g_vh)[i] = vb;
        }
        return;
    }

    const int w = threadIdx.x >> 5, l = threadIdx.x & 31;
    // scale_embed: this lane's 4 dims for all 20 offsets, fp16 in registers
    uint2 sreg[NOFF];
#pragma unroll
    for (int j = 0; j < NOFF; ++j) {
        float4 f = *(const float4*)(se + j * HDIM + l * 4);
        sreg[j].x = h2u(__floats2half2_rn(f.x, f.y));
        sreg[j].y = h2u(__floats2half2_rn(f.z, f.w));
    }
    const float sc = 0.088388347648318447f;
    const int q0i = ((blockIdx.x - CVT_BLOCKS) * 8 + w) * WQ;
    for (int iq = 0; iq < WQ; ++iq) {
        const int gq = q0i + iq;
        const float4 qv = *(const float4*)(q + (size_t)gq * HDIM + l * 4);
        const float a0 = qv.x * sc, a1 = qv.y * sc, a2 = qv.z * sc, a3 = qv.w * sc;
        float acc[NOFF];
#pragma unroll
        for (int j = 0; j < NOFF; ++j) {
            const float2 f01 = __half22float2(*(const __half2*)&sreg[j].x);
            const float2 f23 = __half22float2(*(const __half2*)&sreg[j].y);
            acc[j] = fmaf(a0, f01.x, fmaf(a1, f01.y, fmaf(a2, f23.x, a3 * f23.y)));
        }
        unsigned long long u[10];
#pragma unroll
        for (int m = 0; m < 10; ++m) u[m] = f2pack(acc[2 * m], acc[2 * m + 1]);
#pragma unroll
        for (int m = 0; m < 10; ++m) u[m] = f2add(u[m], __shfl_xor_sync(0xffffffffu, u[m], 16));
#pragma unroll
        for (int m = 0; m < 10; ++m) u[m] = f2add(u[m], __shfl_xor_sync(0xffffffffu, u[m], 8));
        if (l < 8) {
#pragma unroll
            for (int m = 0; m < 10; ++m) redq[w][l][m] = u[m];
        }
        __syncwarp();
        if (l < NOFF) {
            const int mm = l >> 1;
            unsigned long long t = 0ULL;
#pragma unroll
            for (int i = 0; i < 8; ++i) t = f2add(t, redq[w][i][mm]);
            const float2 tp = f2unpack(t);
            g_qse[(size_t)gq * NOFF + l] = (l & 1) ? tp.y : tp.x;
        }
        __syncwarp();
    }
}

// ==== main: register sliding window (offsets 1..8) + gmem gathers (>=9) ====
__global__ void __launch_bounds__(256, 3) dsqg_main(
    const float* __restrict__ q, const float* __restrict__ pb, float* __restrict__ out)
{
    constexpr int goffs[12] = {9,11,13,15,16,23,32,64,128,256,512,1024};

    __shared__ unsigned long long red2[8][8][10];
    __shared__ __align__(16) float p_s[8][24];
    __shared__ float pb_s[NOFF];

    const int tid = threadIdx.x, w = tid >> 5, l = tid & 31;
    const int bh = blockIdx.x >> 5;                 // 32 blocks per (b,h)
    const int n0 = (blockIdx.x & 31) * 256;
    const int h  = bh & (NH - 1);
    if (tid < NOFF) pb_s[tid] = pb[tid * NH + h];
    __syncthreads();

    const float sc = 0.088388347648318447f;
    const size_t base = (size_t)bh * SEQN * HDIM;
    const __half* kb = g_kh + base;
    const __half* vb = g_vh + base;
    const float*  qb = q + base;
    float*        ob = out + base;
    const size_t  qse0 = (size_t)bh * SEQN * NOFF;
    const int d4 = l * 4;
    const int nbase = n0 + w * MAIN_QPW;            // warp's 32 consecutive queries

    // preload window: kwin[i]/vwin[i] = row nbase-8+i (clamped; masked later)
    uint2 kwin[8], vwin[8];
#pragma unroll
    for (int i = 0; i < 8; ++i) {
        int r = nbase - 8 + i; if (r < 0) r = 0;
        kwin[i] = *(const uint2*)(kb + (size_t)r * HDIM + d4);
        vwin[i] = *(const uint2*)(vb + (size_t)r * HDIM + d4);
    }

#pragma unroll 1
    for (int it = 0; it < MAIN_QPW; ++it) {
        const int n = nbase + it;

        const float4 qv = *(const float4*)(qb + (size_t)n * HDIM + d4);
        float myqse = 0.f, mypb = 0.f;
        if (l < NOFF) {
            myqse = g_qse[qse0 + (size_t)n * NOFF + l];
            mypb  = pb_s[l];
        }
        const float q0 = qv.x * sc, q1 = qv.y * sc, q2 = qv.z * sc, q3 = qv.w * sc;

        float acc[NOFF];
        // gmem k dots (offsets >= 9)
#pragma unroll
        for (int t = 0; t < 12; ++t) {
            int kp = n - goffs[t]; if (kp < 0) kp = 0;
            const uint2 kk = *(const uint2*)(kb + (size_t)kp * HDIM + d4);
            const float2 f01 = __half22float2(*(const __half2*)&kk.x);
            const float2 f23 = __half22float2(*(const __half2*)&kk.y);
            acc[8 + t] = fmaf(q0, f01.x, fmaf(q1, f01.y, fmaf(q2, f23.x, q3 * f23.y)));
        }
        // window k dots: offset d -> row n-d = kwin[8-d]
#pragma unroll
        for (int d = 1; d <= 8; ++d) {
            const uint2 kk = kwin[8 - d];
            const float2 f01 = __half22float2(*(const __half2*)&kk.x);
            const float2 f23 = __half22float2(*(const __half2*)&kk.y);
            acc[d - 1] = fmaf(q0, f01.x, fmaf(q1, f01.y, fmaf(q2, f23.x, q3 * f23.y)));
        }

        // transpose reduce (R6)
        unsigned long long uu[10];
#pragma unroll
        for (int m = 0; m < 10; ++m) uu[m] = f2pack(acc[2 * m], acc[2 * m + 1]);
#pragma unroll
        for (int m = 0; m < 10; ++m) uu[m] = f2add(uu[m], __shfl_xor_sync(0xffffffffu, uu[m], 16));
#pragma unroll
        for (int m = 0; m < 10; ++m) uu[m] = f2add(uu[m], __shfl_xor_sync(0xffffffffu, uu[m], 8));
        if (l < 8) {
#pragma unroll
            for (int m = 0; m < 10; ++m) red2[w][l][m] = uu[m];
        }
        __syncwarp();

        float e = 0.f;
        if (l < NOFF) {
            const int mm = l >> 1;
            unsigned long long t = 0ULL;
#pragma unroll
            for (int i = 0; i < 8; ++i) t = f2add(t, red2[w][i][mm]);
            const float2 tp = f2unpack(t);
            const float s = (((l & 1)) ? tp.y : tp.x) + myqse + mypb;
            if (n >= c_offs[l]) e = __expf(s);   // no max pass: |s| << 88
        }
        float lsum = e;
#pragma unroll
        for (int o = 16; o; o >>= 1) lsum += __shfl_xor_sync(0xffffffffu, lsum, o);
        if (l < NOFF) p_s[w][l] = e * (lsum > 0.f ? 1.f / lsum : 0.f);
        __syncwarp();

        // v side
        const float4 pA = *(const float4*)&p_s[w][0];
        const float4 pB = *(const float4*)&p_s[w][4];
        const float4 pC = *(const float4*)&p_s[w][8];
        const float4 pD = *(const float4*)&p_s[w][12];
        const float4 pE = *(const float4*)&p_s[w][16];
        const float pw8[8]  = {pA.x,pA.y,pA.z,pA.w,pB.x,pB.y,pB.z,pB.w};
        const float pg12[12] = {pC.x,pC.y,pC.z,pC.w,pD.x,pD.y,pD.z,pD.w,pE.x,pE.y,pE.z,pE.w};

        float o0 = 0.f, o1 = 0.f, o2 = 0.f, o3 = 0.f;
#pragma unroll
        for (int t = 0; t < 12; ++t) {
            int kp = n - goffs[t]; if (kp < 0) kp = 0;
            const uint2 vv = *(const uint2*)(vb + (size_t)kp * HDIM + d4);
            const float2 f01 = __half22float2(*(const __half2*)&vv.x);
            const float2 f23 = __half22float2(*(const __half2*)&vv.y);
            const float pj = pg12[t];
            o0 = fmaf(pj, f01.x, o0);
            o1 = fmaf(pj, f01.y, o1);
            o2 = fmaf(pj, f23.x, o2);
            o3 = fmaf(pj, f23.y, o3);
        }
#pragma unroll
        for (int d = 1; d <= 8; ++d) {
            const uint2 vv = vwin[8 - d];
            const float2 f01 = __half22float2(*(const __half2*)&vv.x);
            const float2 f23 = __half22float2(*(const __half2*)&vv.y);
            const float pj = pw8[d - 1];
            o0 = fmaf(pj, f01.x, o0);
            o1 = fmaf(pj, f01.y, o1);
            o2 = fmaf(pj, f23.x, o2);
            o3 = fmaf(pj, f23.y, o3);
        }
        *(float4*)(ob + (size_t)n * HDIM + d4) = make_float4(o0, o1, o2, o3);

        // slide window: append row n
#pragma unroll
        for (int i = 0; i < 7; ++i) { kwin[i] = kwin[i + 1]; vwin[i] = vwin[i + 1]; }
        kwin[7] = *(const uint2*)(kb + (size_t)n * HDIM + d4);
        vwin[7] = *(const uint2*)(vb + (size_t)n * HDIM + d4);
        __syncwarp();   // red2 / p_s safe for next iteration
    }
}

extern "C" void kernel_launch(void* const* d_in, const int* in_sizes, int n_in,
                              void* d_out, int out_size) {
    const float* q  = (const float*)d_in[0];
    const float* k  = (const float*)d_in[1];
    const float* v  = (const float*)d_in[2];
    const float* pb = (const float*)d_in[3];
    const float* se = (const float*)d_in[4];
    (void)in_sizes; (void)n_in; (void)out_size;

    prep<<<CVT_BLOCKS + QSE_BLOCKS, 256>>>(q, k, v, se);
    dsqg_main<<<NQ / 256, 256>>>(q, pb, (float*)d_out);
}